// round 4
// baseline (speedup 1.0000x reference)
#include <cuda_runtime.h>
#include <cstdint>

#define B_     8
#define S_     2048
#define N_     4096
#define D_     256
#define MAX_W_ 16
#define SLOTS  (D_ / 4)     // 64 float4 slots per row
#define CHUNK  32
#define NCH    (S_ / CHUNK) // 64 chunks

// Scratch (static device globals — no runtime allocation).
__device__ float  g_prefix[(size_t)B_ * S_ * D_];       // 16.8 MB, fp32 inclusive prefix over S
__device__ double g_csum  [(size_t)B_ * NCH * D_];      // 1 MB, per-chunk sums (fp64)
__device__ double g_coff  [(size_t)B_ * NCH * D_];      // 1 MB, exclusive chunk offsets (fp64)

// ── K1: per-chunk column sums in fp64 ────────────────────────────────────────
// thread = (b, chunk, slot); 8*64*64 = 32768 threads.
__global__ __launch_bounds__(256) void k1_chunk_sums(const float4* __restrict__ seq4)
{
    const int tid  = blockIdx.x * 256 + threadIdx.x;
    const int slot = tid & (SLOTS - 1);
    const int p    = tid >> 6;            // (b, chunk)
    const int ch   = p & (NCH - 1);
    const int b    = p >> 6;

    const float4* __restrict__ q =
        seq4 + ((size_t)b * S_ + (size_t)ch * CHUNK) * SLOTS + slot;

    double s0 = 0.0, s1 = 0.0, s2 = 0.0, s3 = 0.0;
#pragma unroll
    for (int r = 0; r < CHUNK; ++r) {
        const float4 v = __ldg(q + r * SLOTS);
        s0 += v.x; s1 += v.y; s2 += v.z; s3 += v.w;
    }

    double* __restrict__ o = g_csum + (((size_t)b * NCH + ch) * D_) + slot * 4;
    o[0] = s0; o[1] = s1; o[2] = s2; o[3] = s3;
}

// ── K2: Kogge-Stone exclusive scan over 64 chunk sums, per (b,d) column ──────
// block = 256 threads = 4 columns x 64 chunks; grid = (B*D)/4 = 512.
__global__ __launch_bounds__(256) void k2_scan_chunks()
{
    __shared__ double sm[4][NCH];
    const int ch  = threadIdx.x & (NCH - 1);
    const int cl  = threadIdx.x >> 6;                  // column within block
    const int col = blockIdx.x * 4 + cl;               // 0 .. B*D-1
    const int b   = col >> 8;                          // D_ = 256
    const int d   = col & (D_ - 1);

    const size_t idx = (((size_t)b * NCH + ch) * D_) + d;
    const double v = g_csum[idx];
    sm[cl][ch] = v;
    __syncthreads();

#pragma unroll
    for (int off = 1; off < NCH; off <<= 1) {
        const double add = (ch >= off) ? sm[cl][ch - off] : 0.0;
        __syncthreads();
        sm[cl][ch] += add;
        __syncthreads();
    }

    g_coff[idx] = sm[cl][ch] - v;   // exclusive offset
}

// ── K3: materialize fp32 prefix rows (fp64 running sum per chunk) ────────────
// thread = (b, chunk, slot); same mapping as K1.
__global__ __launch_bounds__(256) void k3_write_prefix(const float4* __restrict__ seq4)
{
    const int tid  = blockIdx.x * 256 + threadIdx.x;
    const int slot = tid & (SLOTS - 1);
    const int p    = tid >> 6;
    const int ch   = p & (NCH - 1);
    const int b    = p >> 6;

    const double* __restrict__ off = g_coff + (((size_t)b * NCH + ch) * D_) + slot * 4;
    double s0 = off[0], s1 = off[1], s2 = off[2], s3 = off[3];

    const size_t base = ((size_t)b * S_ + (size_t)ch * CHUNK) * SLOTS + slot;
    const float4* __restrict__ q = seq4 + base;
    float4* __restrict__ pp = reinterpret_cast<float4*>(g_prefix) + base;

#pragma unroll
    for (int r = 0; r < CHUNK; ++r) {
        const float4 v = __ldg(q + r * SLOTS);
        s0 += v.x; s1 += v.y; s2 += v.z; s3 += v.w;
        pp[r * SLOTS] = make_float4((float)s0, (float)s1, (float)s2, (float)s3);
    }
}

// ── K4: span kernel — one warp per span, 2 prefix-row reads ──────────────────
__global__ __launch_bounds__(256) void k4_spans(
    const int2* __restrict__ spans,     // [B, N]
    float4*     __restrict__ out4)      // [B, N, D/4]
{
    const int span = blockIdx.x * 8 + (threadIdx.x >> 5);
    const int lane = threadIdx.x & 31;
    const int b    = span >> 12;        // N_ = 4096

    const int2 se   = spans[span];
    const int start = se.x;
    const int end   = se.y;
    // mask(w) = (w <= width) && (end - w >= 0)  ==  w <= m, m = min(width, end)
    const int m   = min(end - start, end);
    const int low = end - m;            // lowest summed row; rows [low, end], count m+1

    const float4* __restrict__ Pb =
        reinterpret_cast<const float4*>(g_prefix) + (size_t)b * S_ * SLOTS;

    const float4 hi0 = __ldg(&Pb[(size_t)end * SLOTS + lane]);
    const float4 hi1 = __ldg(&Pb[(size_t)end * SLOTS + lane + 32]);

    float4 lo0 = make_float4(0.f, 0.f, 0.f, 0.f);
    float4 lo1 = lo0;
    if (low > 0) {                      // warp-uniform predicate
        lo0 = __ldg(&Pb[(size_t)(low - 1) * SLOTS + lane]);
        lo1 = __ldg(&Pb[(size_t)(low - 1) * SLOTS + lane + 32]);
    }

    const float inv = 1.0f / fmaxf((float)(m + 1), 1e-13f);
    float4 r0, r1;
    r0.x = (hi0.x - lo0.x) * inv; r0.y = (hi0.y - lo0.y) * inv;
    r0.z = (hi0.z - lo0.z) * inv; r0.w = (hi0.w - lo0.w) * inv;
    r1.x = (hi1.x - lo1.x) * inv; r1.y = (hi1.y - lo1.y) * inv;
    r1.z = (hi1.z - lo1.z) * inv; r1.w = (hi1.w - lo1.w) * inv;

    float4* __restrict__ o = out4 + (size_t)span * SLOTS + lane;
    o[0]  = r0;
    o[32] = r1;
}

extern "C" void kernel_launch(void* const* d_in, const int* in_sizes, int n_in,
                              void* d_out, int out_size)
{
    const float4* seq4  = (const float4*)d_in[0];  // sequence_tensor [B,S,D] f32
    const int2*   spans = (const int2*)  d_in[1];  // span_indices    [B,N,2] i32
    float4*       out4  = (float4*)d_out;          // [B,N,D] f32

    const int nthreads = B_ * NCH * SLOTS;         // 32768
    k1_chunk_sums <<<nthreads / 256, 256>>>(seq4);
    k2_scan_chunks<<<(B_ * D_) / 4,  256>>>();
    k3_write_prefix<<<nthreads / 256, 256>>>(seq4);
    k4_spans      <<<(B_ * N_) / 8,  256>>>(spans, out4);
}

// round 5
// speedup vs baseline: 3.6065x; 3.6065x over previous
#include <cuda_runtime.h>
#include <cstdint>

#define B_     8
#define S_     2048
#define N_     4096
#define D_     256
#define SLOTS  (D_ / 4)      // 64 float4 per row
#define BLK    16            // prefix block = 16 rows (>= max span extent)
#define NBLK   (S_ / BLK)    // 128 blocks per batch

// Scratch: block-local inclusive prefix and block totals (fp32 only).
__device__ float g_P[(size_t)B_ * S_ * D_];          // 16.8 MB
__device__ float g_T[(size_t)B_ * NBLK * D_];        // 1 MB

// ── K1: per-16-row-block inclusive prefix + block total ─────────────────────
// thread = (b, blk, slot); 8*128*64 = 65536 threads, grid 512 x 128.
__global__ __launch_bounds__(128) void k_prep(const float4* __restrict__ seq4)
{
    const int tid  = blockIdx.x * 128 + threadIdx.x;
    const int slot = tid & (SLOTS - 1);
    const int p    = tid >> 6;                 // (b, blk)
    const int blk  = p & (NBLK - 1);
    const int b    = p >> 7;                   // NBLK = 128

    const size_t base = ((size_t)b * S_ + (size_t)blk * BLK) * SLOTS + slot;
    const float4* __restrict__ q = seq4 + base;
    float4* __restrict__ Pp = reinterpret_cast<float4*>(g_P) + base;

    float4 s = make_float4(0.f, 0.f, 0.f, 0.f);
#pragma unroll
    for (int r = 0; r < BLK; ++r) {
        const float4 v = __ldg(q + r * SLOTS);
        s.x += v.x; s.y += v.y; s.z += v.z; s.w += v.w;
        Pp[r * SLOTS] = s;
    }
    reinterpret_cast<float4*>(g_T)[((size_t)b * NBLK + blk) * SLOTS + slot] = s;
}

// ── K2: spans — 16 threads per span, 4 float4 each; <=3 small-sum operands ──
// blockDim 256 -> 16 spans/block, grid = 2048.
__global__ __launch_bounds__(256) void k_spans(
    const int2* __restrict__ spans,     // [B, N]
    float4*     __restrict__ out4)      // [B, N, D/4]
{
    const int span = blockIdx.x * 16 + (threadIdx.x >> 4);
    const int t    = threadIdx.x & 15;          // owns slots t, t+16, t+32, t+48
    const int b    = span >> 12;                // N_ = 4096

    const int2 se  = spans[span];               // broadcast within half-warp
    const int end  = se.y;
    const int m    = min(end - se.x, end);      // mask(w) <=> w <= m
    const int low  = end - m;                   // rows [low, end], count m+1

    const bool haveSub = (low & (BLK - 1)) != 0;        // need P[low-1]
    const bool cross   = (low >> 4) != (end >> 4);      // need T[blk(end)-1]

    const float4* __restrict__ Pb =
        reinterpret_cast<const float4*>(g_P) + (size_t)b * S_ * SLOTS;
    const float4* __restrict__ pe = Pb + (size_t)end * SLOTS + t;
    const float4* __restrict__ ps = Pb + (size_t)(low - 1) * SLOTS + t;   // valid iff haveSub
    const float4* __restrict__ pt =
        reinterpret_cast<const float4*>(g_T)
        + ((size_t)b * NBLK + ((end >> 4) - 1)) * SLOTS + t;              // valid iff cross

    const float inv = 1.0f / fmaxf((float)(m + 1), 1e-13f);
    const float4 z  = make_float4(0.f, 0.f, 0.f, 0.f);

    float4* __restrict__ o = out4 + (size_t)span * SLOTS + t;

#pragma unroll
    for (int i = 0; i < 4; ++i) {
        const float4 hi = __ldg(pe + i * 16);
        const float4 tb = cross   ? __ldg(pt + i * 16) : z;
        const float4 sb = haveSub ? __ldg(ps + i * 16) : z;
        float4 r;
        r.x = (hi.x + tb.x - sb.x) * inv;
        r.y = (hi.y + tb.y - sb.y) * inv;
        r.z = (hi.z + tb.z - sb.z) * inv;
        r.w = (hi.w + tb.w - sb.w) * inv;
        o[i * 16] = r;
    }
}

extern "C" void kernel_launch(void* const* d_in, const int* in_sizes, int n_in,
                              void* d_out, int out_size)
{
    const float4* seq4  = (const float4*)d_in[0];  // sequence_tensor [B,S,D] f32
    const int2*   spans = (const int2*)  d_in[1];  // span_indices    [B,N,2] i32
    float4*       out4  = (float4*)d_out;          // [B,N,D] f32

    k_prep <<<(B_ * NBLK * SLOTS) / 128, 128>>>(seq4);
    k_spans<<<(B_ * N_) / 16, 256>>>(spans, out4);
}